// round 1
// baseline (speedup 1.0000x reference)
#include <cuda_runtime.h>

#define N0   292864
#define N1   11264
#define N2   1024
#define F0   25
#define F1   10
#define DIN  256
#define DHID 256
#define NCLS 128

// ---------------- scratch (no cudaMalloc allowed) ----------------
__device__ float g_V0[(size_t)N1 * 512];   // [self(256) | neigh_mean(256)] per needed row (compacted)
__device__ float g_H [(size_t)N1 * 256];   // hidden activations (only needed rows written)
__device__ float g_V1[(size_t)N2 * 512];   // layer-1 input rows
__device__ float g_P [(size_t)4 * N2 * NCLS]; // split-K partials for layer-1 GEMM
__device__ int           g_rowlist[N1];
__device__ unsigned char g_need[N1];
__device__ int           g_cnt;

// ---------------- mask / compaction ----------------
__global__ void k_zero() {
    int i = blockIdx.x * 256 + threadIdx.x;
    if (i < N1) g_need[i] = 0;
    if (i == 0) g_cnt = 0;
}

__global__ void k_mark(const int* __restrict__ col1) {
    int i = blockIdx.x * 256 + threadIdx.x;
    if (i < N2 * F1) g_need[col1[i]] = 1;
    if (i < N2)      g_need[i] = 1;
}

__global__ void k_compact() {
    int j = blockIdx.x * 256 + threadIdx.x;
    if (j < N1 && g_need[j]) {
        int p = atomicAdd(&g_cnt, 1);
        g_rowlist[p] = j;
    }
}

// ---------------- layer 0 gather + neighbor mean (compacted output) ----------------
__global__ void k_gather0(const float* __restrict__ emb,
                          const int*   __restrict__ gid0,
                          const int*   __restrict__ col0) {
    int r = blockIdx.x;
    if (r >= g_cnt) return;
    int j = g_rowlist[r];
    int t = threadIdx.x;                       // 256 threads = one feature each (coalesced 1KB row reads)

    g_V0[(size_t)r * 512 + t] = emb[(size_t)gid0[j] * DIN + t];

    float acc = 0.f;
    const int* cb = col0 + (size_t)j * F0;
    #pragma unroll
    for (int f = 0; f < F0; f++) {
        int c = cb[f];
        int g = gid0[c];
        acc += emb[(size_t)g * DIN + t];
    }
    g_V0[(size_t)r * 512 + 256 + t] = acc * (1.f / F0);
}

// ---------------- layer 0 GEMM: H = relu(V0 @ [Wself;Wneigh] + b0) ----------------
// 128x128 tile, BK=16, 256 threads, 8x8 per thread.
__global__ __launch_bounds__(256, 2)
void k_gemm0(const float* __restrict__ Wself,
             const float* __restrict__ Wneigh,
             const float* __restrict__ b0) {
    const int cnt = g_cnt;
    const int r0 = blockIdx.x * 128;
    if (r0 >= cnt) return;
    const int n0 = blockIdx.y * 128;

    __shared__ float As[16][128];
    __shared__ float Bs[16][128];
    __shared__ int   jrow[128];
    __shared__ float bsh[128];

    const int tid = threadIdx.x;
    if (tid < 128) {
        int r = r0 + tid;
        jrow[tid] = (r < cnt) ? g_rowlist[r] : 0;
        bsh[tid]  = b0[n0 + tid];
    }
    const int tx = tid & 15, ty = tid >> 4;

    float acc[8][8];
    #pragma unroll
    for (int i = 0; i < 8; i++)
        #pragma unroll
        for (int j = 0; j < 8; j++) acc[i][j] = 0.f;

    for (int kt = 0; kt < 32; kt++) {
        const int k0 = kt * 16;
        // A tile: 128 rows x 16 k  (rows beyond cnt read stale-but-in-bounds data; stores are guarded)
        #pragma unroll
        for (int i = 0; i < 2; i++) {
            int v = tid + i * 256;
            int m = v >> 2, kq = v & 3;
            float4 a = *(const float4*)&g_V0[(size_t)(r0 + m) * 512 + k0 + kq * 4];
            As[kq * 4 + 0][m] = a.x; As[kq * 4 + 1][m] = a.y;
            As[kq * 4 + 2][m] = a.z; As[kq * 4 + 3][m] = a.w;
        }
        // B tile: concatenated weight [512,256]; BK=16 never straddles the 256 boundary
        const float* B = (k0 < 256) ? (Wself + (size_t)k0 * DHID)
                                    : (Wneigh + (size_t)(k0 - 256) * DHID);
        #pragma unroll
        for (int i = 0; i < 2; i++) {
            int v = tid + i * 256;
            int kk = v >> 5, c4 = v & 31;
            *(float4*)&Bs[kk][c4 * 4] = *(const float4*)&B[(size_t)kk * DHID + n0 + c4 * 4];
        }
        __syncthreads();

        #pragma unroll
        for (int kk = 0; kk < 16; kk++) {
            float a[8], b[8];
            #pragma unroll
            for (int s = 0; s < 4; s++) {
                a[s]     = As[kk][ty * 4 + s];
                a[4 + s] = As[kk][64 + ty * 4 + s];
                b[s]     = Bs[kk][tx * 4 + s];
                b[4 + s] = Bs[kk][64 + tx * 4 + s];
            }
            #pragma unroll
            for (int i = 0; i < 8; i++)
                #pragma unroll
                for (int j = 0; j < 8; j++) acc[i][j] += a[i] * b[j];
        }
        __syncthreads();
    }

    #pragma unroll
    for (int i = 0; i < 8; i++) {
        int m = (i < 4) ? (ty * 4 + i) : (64 + ty * 4 + (i - 4));
        int r = r0 + m;
        if (r < cnt) {
            float* Hp = g_H + (size_t)jrow[m] * 256 + n0;
            #pragma unroll
            for (int j = 0; j < 8; j++) {
                int n = (j < 4) ? (tx * 4 + j) : (64 + tx * 4 + (j - 4));
                float v = acc[i][j] + bsh[n];
                Hp[n] = v > 0.f ? v : 0.f;
            }
        }
    }
}

// ---------------- layer 1 gather + neighbor mean ----------------
__global__ void k_gather1(const int* __restrict__ col1) {
    int i = blockIdx.x;
    int t = threadIdx.x;
    g_V1[(size_t)i * 512 + t] = g_H[(size_t)i * 256 + t];
    float acc = 0.f;
    #pragma unroll
    for (int f = 0; f < F1; f++) {
        int c = col1[i * F1 + f];
        acc += g_H[(size_t)c * 256 + t];
    }
    g_V1[(size_t)i * 512 + 256 + t] = acc * (1.f / F1);
}

// ---------------- layer 1 GEMM (split-K=4 into partials, deterministic) ----------------
// 32x128 tile, BK=16, 256 threads, 4x4 per thread. K chunk = 128 per CTA.
__global__ __launch_bounds__(256)
void k_gemm1(const float* __restrict__ Wself, const float* __restrict__ Wneigh) {
    const int r0 = blockIdx.x * 32;
    const int ks = blockIdx.y;           // 0..3 -> K range [ks*128, ks*128+128)
    const int kbase = ks * 128;

    __shared__ float As[32][17];         // [m][kk], padded; a-reads broadcast within warp
    __shared__ float Bs[16][128];

    const int tid = threadIdx.x;
    const int tx = tid & 31, ty = tid >> 5;

    float acc[4][4];
    #pragma unroll
    for (int i = 0; i < 4; i++)
        #pragma unroll
        for (int j = 0; j < 4; j++) acc[i][j] = 0.f;

    for (int kt = 0; kt < 8; kt++) {
        const int k0 = kbase + kt * 16;
        #pragma unroll
        for (int i = 0; i < 2; i++) {
            int v = tid + i * 256;
            int kk = v & 15, m = v >> 4;
            As[m][kk] = g_V1[(size_t)(r0 + m) * 512 + k0 + kk];
        }
        const float* B = (k0 < 256) ? (Wself + (size_t)k0 * NCLS)
                                    : (Wneigh + (size_t)(k0 - 256) * NCLS);
        #pragma unroll
        for (int i = 0; i < 2; i++) {
            int v = tid + i * 256;
            int kk = v >> 5, c4 = v & 31;
            *(float4*)&Bs[kk][c4 * 4] = *(const float4*)&B[(size_t)kk * NCLS + c4 * 4];
        }
        __syncthreads();

        #pragma unroll
        for (int kk = 0; kk < 16; kk++) {
            float a[4], b[4];
            #pragma unroll
            for (int s = 0; s < 4; s++) {
                a[s] = As[ty * 4 + s][kk];
                b[s] = Bs[kk][tx * 4 + s];
            }
            #pragma unroll
            for (int i = 0; i < 4; i++)
                #pragma unroll
                for (int j = 0; j < 4; j++) acc[i][j] += a[i] * b[j];
        }
        __syncthreads();
    }

    float* P = g_P + (size_t)ks * N2 * NCLS;
    #pragma unroll
    for (int i = 0; i < 4; i++) {
        int r = r0 + ty * 4 + i;
        #pragma unroll
        for (int j = 0; j < 4; j++)
            P[(size_t)r * NCLS + tx * 4 + j] = acc[i][j];
    }
}

__global__ void k_reduce(const float* __restrict__ b1, float* __restrict__ out) {
    int i = blockIdx.x * 256 + threadIdx.x;   // < N2*NCLS = 131072
    float v = g_P[i]
            + g_P[(size_t)N2 * NCLS + i]
            + g_P[(size_t)2 * N2 * NCLS + i]
            + g_P[(size_t)3 * N2 * NCLS + i]
            + b1[i & (NCLS - 1)];
    out[i] = v;
}

// ---------------- launch ----------------
extern "C" void kernel_launch(void* const* d_in, const int* in_sizes, int n_in,
                              void* d_out, int out_size) {
    const float* emb  = (const float*)d_in[0];
    const int*   gid0 = (const int*)  d_in[1];
    const int*   col0 = (const int*)  d_in[2];
    const int*   col1 = (const int*)  d_in[3];
    const float* Ws0  = (const float*)d_in[4];
    const float* Wn0  = (const float*)d_in[5];
    const float* b0   = (const float*)d_in[6];
    const float* Ws1  = (const float*)d_in[7];
    const float* Wn1  = (const float*)d_in[8];
    const float* b1   = (const float*)d_in[9];
    float* out = (float*)d_out;

    k_zero   <<<(N1 + 255) / 256, 256>>>();
    k_mark   <<<(N2 * F1 + 255) / 256, 256>>>(col1);
    k_compact<<<(N1 + 255) / 256, 256>>>();
    k_gather0<<<N1, 256>>>(emb, gid0, col0);
    k_gemm0  <<<dim3((N1 + 127) / 128, DHID / 128), 256>>>(Ws0, Wn0, b0);
    k_gather1<<<N2, 256>>>(col1);
    k_gemm1  <<<dim3(N2 / 32, 4), 256>>>(Ws1, Wn1);
    k_reduce <<<(N2 * NCLS) / 256, 256>>>(b1, out);
}

// round 5
// speedup vs baseline: 1.8446x; 1.8446x over previous
#include <cuda_runtime.h>
#include <cstdint>

#define N0   292864
#define N1   11264
#define N2   1024
#define F0   25
#define F1   10
#define DIN  256
#define DHID 256
#define NCLS 128

// ---------------- scratch (no cudaMalloc allowed) ----------------
__device__ float g_V0[(size_t)N1 * 512];      // [self(256) | neigh_mean(256)] per needed row (tf32-rounded)
__device__ float g_W0t[(size_t)DHID * 512];   // layer-0 weights, transposed [n][k], tf32-rounded
__device__ float g_H [(size_t)N1 * 256];      // hidden activations (only needed rows written)
__device__ float g_V1[(size_t)N2 * 512];      // layer-1 input rows
__device__ float g_P [(size_t)4 * N2 * NCLS]; // split-K partials for layer-1 GEMM
__device__ int           g_rowlist[N1];
__device__ unsigned char g_need[N1];
__device__ int           g_cnt;

// ---------------- helpers ----------------
__device__ __forceinline__ uint32_t smem_u32(const void* p) {
    uint32_t a;
    asm("{ .reg .u64 t; cvta.to.shared.u64 t, %1; cvt.u32.u64 %0, t; }" : "=r"(a) : "l"(p));
    return a;
}
__device__ __forceinline__ float frna(float x) {   // f32 -> tf32 round-to-nearest, kept in f32 container
    uint32_t u;
    asm("cvt.rna.tf32.f32 %0, %1;" : "=r"(u) : "f"(x));
    return __uint_as_float(u);
}
__device__ __forceinline__ float4 frna4(float4 v) {
    v.x = frna(v.x); v.y = frna(v.y); v.z = frna(v.z); v.w = frna(v.w);
    return v;
}
__device__ __forceinline__ void cpa16(uint32_t dst, const void* src) {
    asm volatile("cp.async.cg.shared.global [%0], [%1], 16;" :: "r"(dst), "l"(src));
}
#define CP_COMMIT() asm volatile("cp.async.commit_group;" ::: "memory")
#define CP_WAIT(n)  asm volatile("cp.async.wait_group %0;" :: "n"(n) : "memory")

#define LDSM4(r, a)                                                              \
    asm volatile("ldmatrix.sync.aligned.m8n8.x4.shared.b16 {%0,%1,%2,%3}, [%4];" \
        : "=r"((r)[0]), "=r"((r)[1]), "=r"((r)[2]), "=r"((r)[3]) : "r"(a))

#define MMA_TF32(c, a, b)                                                        \
    asm volatile("mma.sync.aligned.m16n8k8.row.col.f32.tf32.tf32.f32 "           \
        "{%0,%1,%2,%3}, {%4,%5,%6,%7}, {%8,%9}, {%0,%1,%2,%3};"                  \
        : "+f"((c)[0]), "+f"((c)[1]), "+f"((c)[2]), "+f"((c)[3])                 \
        : "r"((a)[0]), "r"((a)[1]), "r"((a)[2]), "r"((a)[3]),                    \
          "r"((b)[0]), "r"((b)[1]))

// ---------------- mask / compaction ----------------
__global__ void k_zero() {
    int i = blockIdx.x * 256 + threadIdx.x;
    if (i < N1) g_need[i] = 0;
    if (i == 0) g_cnt = 0;
}
__global__ void k_mark(const int* __restrict__ col1) {
    int i = blockIdx.x * 256 + threadIdx.x;
    if (i < N2 * F1) g_need[col1[i]] = 1;
    if (i < N2)      g_need[i] = 1;
}
__global__ void k_compact() {
    int j = blockIdx.x * 256 + threadIdx.x;
    if (j < N1 && g_need[j]) {
        int p = atomicAdd(&g_cnt, 1);
        g_rowlist[p] = j;
    }
}

// ---------------- weight prep: g_W0t[n][k] = tf32(W[k][n]), W = [Ws0; Wn0] ----------------
__global__ __launch_bounds__(256)
void k_prep(const float* __restrict__ Ws0, const float* __restrict__ Wn0) {
    __shared__ float t[32][33];
    const int bk = blockIdx.x * 32;   // k block (0..511)
    const int bn = blockIdx.y * 32;   // n block (0..255)
    const int tx = threadIdx.x & 31, ty = threadIdx.x >> 5;   // 32 x 8
    const float* W = (bk < 256) ? (Ws0 + (size_t)bk * DHID) : (Wn0 + (size_t)(bk - 256) * DHID);
    #pragma unroll
    for (int i = 0; i < 32; i += 8)
        t[ty + i][tx] = W[(size_t)(ty + i) * DHID + bn + tx];
    __syncthreads();
    #pragma unroll
    for (int i = 0; i < 32; i += 8)
        g_W0t[(size_t)(bn + ty + i) * 512 + bk + tx] = frna(t[tx][ty + i]);
}

// ---------------- layer 0 gather: 4 rows/CTA, 64 threads/row, float4 ----------------
__global__ __launch_bounds__(256)
void k_gather0(const float* __restrict__ emb,
               const int*   __restrict__ gid0,
               const int*   __restrict__ col0) {
    __shared__ int gsh[4][26];
    const int cnt = g_cnt;
    const int rb = blockIdx.x * 4;
    const int tid = threadIdx.x;

    if (tid < 128) {
        int row = tid >> 5, f = tid & 31;
        int r = rb + row;
        if (f < 26 && r < cnt) {
            int j = g_rowlist[r];
            int c = (f == 0) ? j : col0[(size_t)j * F0 + (f - 1)];
            gsh[row][f] = gid0[c];
        }
    }
    __syncthreads();

    const int row = tid >> 6, l = tid & 63;
    const int r = rb + row;
    if (r >= cnt) return;

    const float4* E = (const float4*)emb;   // row stride 64
    float4* V = (float4*)g_V0;              // row stride 128

    float4 s = E[(size_t)gsh[row][0] * 64 + l];
    V[(size_t)r * 128 + l] = frna4(s);

    float4 a0 = {0,0,0,0}, a1 = {0,0,0,0}, a2 = {0,0,0,0}, a3 = {0,0,0,0};
    #pragma unroll
    for (int f = 1; f < 26; f += 4) {
        float4 t0 = E[(size_t)gsh[row][f] * 64 + l];
        a0.x += t0.x; a0.y += t0.y; a0.z += t0.z; a0.w += t0.w;
        if (f + 1 < 26) {
            float4 t1 = E[(size_t)gsh[row][f + 1] * 64 + l];
            a1.x += t1.x; a1.y += t1.y; a1.z += t1.z; a1.w += t1.w;
        }
        if (f + 2 < 26) {
            float4 t2 = E[(size_t)gsh[row][f + 2] * 64 + l];
            a2.x += t2.x; a2.y += t2.y; a2.z += t2.z; a2.w += t2.w;
        }
        if (f + 3 < 26) {
            float4 t3 = E[(size_t)gsh[row][f + 3] * 64 + l];
            a3.x += t3.x; a3.y += t3.y; a3.z += t3.z; a3.w += t3.w;
        }
    }
    const float sc = 1.f / F0;
    float4 acc;
    acc.x = (a0.x + a1.x + a2.x + a3.x) * sc;
    acc.y = (a0.y + a1.y + a2.y + a3.y) * sc;
    acc.z = (a0.z + a1.z + a2.z + a3.z) * sc;
    acc.w = (a0.w + a1.w + a2.w + a3.w) * sc;
    V[(size_t)r * 128 + 64 + l] = frna4(acc);
}

// ---------------- layer 0 GEMM via mma.sync tf32 ----------------
// CTA 128x128, BK=32, 8 warps (2 m x 4 n), warp tile 64x32, m16n8k8.
// SMEM (1024-aligned base): A stage 16KB + B stage 16KB, x2 stages = 64KB; meta at +65536.
#define G0_SMEM (65536 + 1024 + 1024)

__global__ __launch_bounds__(256, 1)
void k_gemm0_mma(const float* __restrict__ b0) {
    extern __shared__ char smem_raw[];
    const int cnt = g_cnt;
    const int r0 = blockIdx.x * 128;
    if (r0 >= cnt) return;
    const int n0 = blockIdx.y * 128;

    const int tid  = threadIdx.x;
    const int wid  = tid >> 5, lane = tid & 31;
    const int warp_m = wid & 1, warp_n = wid >> 1;

    uint32_t sb0 = smem_u32(smem_raw);
    uint32_t sb  = (sb0 + 1023) & ~1023u;               // 1024-aligned for swizzle
    char* smem   = smem_raw + (sb - sb0);

    int*   jrow = (int*)(smem + 65536);
    float* bsh  = (float*)(smem + 65536 + 512);
    if (tid < 128) {
        int r = r0 + tid;
        jrow[tid] = (r < cnt) ? g_rowlist[r] : 0;
        bsh[tid]  = b0[n0 + tid];
    }

    // per-thread cp.async slots: v in [0,1024): m = v>>3 (row), kq = v&7 (16B chunk)
    const int lm = tid >> 3;        // base row for i=0 slot... recomputed per i below
    (void)lm;

    // ldmatrix lane geometry
    const int rowlA  = (lane & 7) + ((lane >> 3) & 1) * 8;  // A: tiles (m0-7,klo)(m8-15,klo)(m0-7,khi)(m8-15,khi)
    const int khalfA = lane >> 4;
    const int rowlB  = (lane & 7) + (lane >> 4) * 8;        // B: tiles (n0-7,klo)(n0-7,khi)(n8-15,klo)(n8-15,khi)
    const int khalfB = (lane >> 3) & 1;
    const uint32_t axor = (uint32_t)((lane & 7) << 4);

    float acc[4][4][4];
    #pragma unroll
    for (int mt = 0; mt < 4; mt++)
        #pragma unroll
        for (int nt = 0; nt < 4; nt++)
            #pragma unroll
            for (int q = 0; q < 4; q++) acc[mt][nt][q] = 0.f;

    // ---- loader ----
    auto load_tile = [&](int kt, int stage) {
        const int k0 = kt * 32;
        uint32_t As = sb + stage * 32768;
        uint32_t Bs = As + 16384;
        #pragma unroll
        for (int i = 0; i < 4; i++) {
            int v = tid + i * 256;
            int m = v >> 3, kq = v & 7;
            uint32_t off = (uint32_t)(m * 128 + kq * 16);
            off ^= (uint32_t)((m & 7) << 4);
            cpa16(As + off, &g_V0 [(size_t)(r0 + m) * 512 + k0 + kq * 4]);
            cpa16(Bs + off, &g_W0t[(size_t)(n0 + m) * 512 + k0 + kq * 4]);
        }
        CP_COMMIT();
    };

    load_tile(0, 0);

    for (int kt = 0; kt < 16; kt++) {
        if (kt < 15) {
            load_tile(kt + 1, (kt + 1) & 1);
            CP_WAIT(1);
        } else {
            CP_WAIT(0);
        }
        __syncthreads();

        uint32_t As = sb + (kt & 1) * 32768;
        uint32_t Bs = As + 16384;

        #pragma unroll
        for (int ks = 0; ks < 4; ks++) {
            const int kk = ks * 8;
            uint32_t a[4][4], b[4][2];
            #pragma unroll
            for (int mt = 0; mt < 4; mt++) {
                uint32_t off = (uint32_t)((warp_m * 64 + mt * 16 + rowlA) * 128 + khalfA * 16 + kk * 4);
                LDSM4(a[mt], As + (off ^ axor));
            }
            #pragma unroll
            for (int p = 0; p < 2; p++) {
                uint32_t off = (uint32_t)((warp_n * 32 + p * 16 + rowlB) * 128 + khalfB * 16 + kk * 4);
                uint32_t r[4];
                LDSM4(r, Bs + (off ^ axor));
                b[2 * p][0] = r[0]; b[2 * p][1] = r[1];
                b[2 * p + 1][0] = r[2]; b[2 * p + 1][1] = r[3];
            }
            #pragma unroll
            for (int mt = 0; mt < 4; mt++)
                #pragma unroll
                for (int nt = 0; nt < 4; nt++)
                    MMA_TF32(acc[mt][nt], a[mt], b[nt]);
        }
        __syncthreads();
    }

    // epilogue: bias + relu, scatter rows via jrow
    #pragma unroll
    for (int mt = 0; mt < 4; mt++) {
        #pragma unroll
        for (int h = 0; h < 2; h++) {
            int m = warp_m * 64 + mt * 16 + (lane >> 2) + h * 8;
            int r = r0 + m;
            if (r < cnt) {
                float* Hp = g_H + (size_t)jrow[m] * 256 + n0;
                #pragma unroll
                for (int nt = 0; nt < 4; nt++) {
                    int c = warp_n * 32 + nt * 8 + (lane & 3) * 2;
                    float2 o;
                    o.x = acc[mt][nt][h * 2 + 0] + bsh[c];
                    o.y = acc[mt][nt][h * 2 + 1] + bsh[c + 1];
                    o.x = fmaxf(o.x, 0.f);
                    o.y = fmaxf(o.y, 0.f);
                    *(float2*)&Hp[c] = o;
                }
            }
        }
    }
}

// ---------------- layer 1 gather + neighbor mean ----------------
__global__ void k_gather1(const int* __restrict__ col1) {
    int i = blockIdx.x;
    int t = threadIdx.x;
    g_V1[(size_t)i * 512 + t] = g_H[(size_t)i * 256 + t];
    float acc = 0.f;
    #pragma unroll
    for (int f = 0; f < F1; f++) {
        int c = col1[i * F1 + f];
        acc += g_H[(size_t)c * 256 + t];
    }
    g_V1[(size_t)i * 512 + 256 + t] = acc * (1.f / F1);
}

// ---------------- layer 1 GEMM (split-K=4 into partials, deterministic, f32) ----------------
__global__ __launch_bounds__(256)
void k_gemm1(const float* __restrict__ Wself, const float* __restrict__ Wneigh) {
    const int r0 = blockIdx.x * 32;
    const int ks = blockIdx.y;
    const int kbase = ks * 128;

    __shared__ float As[32][17];
    __shared__ float Bs[16][128];

    const int tid = threadIdx.x;
    const int tx = tid & 31, ty = tid >> 5;

    float acc[4][4];
    #pragma unroll
    for (int i = 0; i < 4; i++)
        #pragma unroll
        for (int j = 0; j < 4; j++) acc[i][j] = 0.f;

    for (int kt = 0; kt < 8; kt++) {
        const int k0 = kbase + kt * 16;
        #pragma unroll
        for (int i = 0; i < 2; i++) {
            int v = tid + i * 256;
            int kk = v & 15, m = v >> 4;
            As[m][kk] = g_V1[(size_t)(r0 + m) * 512 + k0 + kk];
        }
        const float* B = (k0 < 256) ? (Wself + (size_t)k0 * NCLS)
                                    : (Wneigh + (size_t)(k0 - 256) * NCLS);
        #pragma unroll
        for (int i = 0; i < 2; i++) {
            int v = tid + i * 256;
            int kk = v >> 5, c4 = v & 31;
            *(float4*)&Bs[kk][c4 * 4] = *(const float4*)&B[(size_t)kk * NCLS + c4 * 4];
        }
        __syncthreads();

        #pragma unroll
        for (int kk = 0; kk < 16; kk++) {
            float a[4], b[4];
            #pragma unroll
            for (int s = 0; s < 4; s++) {
                a[s] = As[ty * 4 + s][kk];
                b[s] = Bs[kk][tx * 4 + s];
            }
            #pragma unroll
            for (int i = 0; i < 4; i++)
                #pragma unroll
                for (int j = 0; j < 4; j++) acc[i][j] += a[i] * b[j];
        }
        __syncthreads();
    }

    float* P = g_P + (size_t)ks * N2 * NCLS;
    #pragma unroll
    for (int i = 0; i < 4; i++) {
        int r = r0 + ty * 4 + i;
        #pragma unroll
        for (int j = 0; j < 4; j++)
            P[(size_t)r * NCLS + tx * 4 + j] = acc[i][j];
    }
}

__global__ void k_reduce(const float* __restrict__ b1, float* __restrict__ out) {
    int i = blockIdx.x * 256 + threadIdx.x;
    float v = g_P[i]
            + g_P[(size_t)N2 * NCLS + i]
            + g_P[(size_t)2 * N2 * NCLS + i]
            + g_P[(size_t)3 * N2 * NCLS + i]
            + b1[i & (NCLS - 1)];
    out[i] = v;
}

// ---------------- launch ----------------
extern "C" void kernel_launch(void* const* d_in, const int* in_sizes, int n_in,
                              void* d_out, int out_size) {
    const float* emb  = (const float*)d_in[0];
    const int*   gid0 = (const int*)  d_in[1];
    const int*   col0 = (const int*)  d_in[2];
    const int*   col1 = (const int*)  d_in[3];
    const float* Ws0  = (const float*)d_in[4];
    const float* Wn0  = (const float*)d_in[5];
    const float* b0   = (const float*)d_in[6];
    const float* Ws1  = (const float*)d_in[7];
    const float* Wn1  = (const float*)d_in[8];
    const float* b1   = (const float*)d_in[9];
    float* out = (float*)d_out;

    cudaFuncSetAttribute(k_gemm0_mma, cudaFuncAttributeMaxDynamicSharedMemorySize, G0_SMEM);

    k_zero     <<<(N1 + 255) / 256, 256>>>();
    k_mark     <<<(N2 * F1 + 255) / 256, 256>>>(col1);
    k_compact  <<<(N1 + 255) / 256, 256>>>();
    k_prep     <<<dim3(16, 8), 256>>>(Ws0, Wn0);
    k_gather0  <<<(N1 + 3) / 4, 256>>>(emb, gid0, col0);
    k_gemm0_mma<<<dim3((N1 + 127) / 128, DHID / 128), 256, G0_SMEM>>>(b0);
    k_gather1  <<<N2, 256>>>(col1);
    k_gemm1    <<<dim3(N2 / 32, 4), 256>>>(Ws1, Wn1);
    k_reduce   <<<(N2 * NCLS) / 256, 256>>>(b1, out);
}

// round 6
// speedup vs baseline: 1.9353x; 1.0492x over previous
#include <cuda_runtime.h>
#include <cstdint>

#define N0   292864
#define N1   11264
#define N2   1024
#define F0   25
#define F1   10
#define DIN  256
#define DHID 256
#define NCLS 128

// ---------------- scratch (no cudaMalloc allowed) ----------------
__device__ float g_V0[(size_t)N1 * 512];      // [self(256) | neigh_mean(256)] per needed row (tf32-rounded)
__device__ float g_W0t[(size_t)DHID * 512];   // layer-0 weights, transposed [n][k], tf32-rounded
__device__ float g_H [(size_t)N1 * 256];      // hidden activations (only needed rows written)
__device__ float g_V1[(size_t)N2 * 512];      // layer-1 input rows
__device__ float g_P [(size_t)4 * N2 * NCLS]; // split-K partials for layer-1 GEMM
__device__ int g_rowlist[N1];
__device__ int g_need[N1];
__device__ int g_cnt;

// ---------------- helpers ----------------
__device__ __forceinline__ uint32_t smem_u32(const void* p) {
    uint32_t a;
    asm("{ .reg .u64 t; cvta.to.shared.u64 t, %1; cvt.u32.u64 %0, t; }" : "=r"(a) : "l"(p));
    return a;
}
__device__ __forceinline__ float frna(float x) {   // f32 -> tf32 round-to-nearest, kept in f32 container
    uint32_t u;
    asm("cvt.rna.tf32.f32 %0, %1;" : "=r"(u) : "f"(x));
    return __uint_as_float(u);
}
__device__ __forceinline__ float4 frna4(float4 v) {
    v.x = frna(v.x); v.y = frna(v.y); v.z = frna(v.z); v.w = frna(v.w);
    return v;
}
__device__ __forceinline__ void cpa16(uint32_t dst, const void* src) {
    asm volatile("cp.async.cg.shared.global [%0], [%1], 16;" :: "r"(dst), "l"(src));
}
#define CP_COMMIT() asm volatile("cp.async.commit_group;" ::: "memory")
#define CP_WAIT(n)  asm volatile("cp.async.wait_group %0;" :: "n"(n) : "memory")

#define LDSM4(r, a)                                                              \
    asm volatile("ldmatrix.sync.aligned.m8n8.x4.shared.b16 {%0,%1,%2,%3}, [%4];" \
        : "=r"((r)[0]), "=r"((r)[1]), "=r"((r)[2]), "=r"((r)[3]) : "r"(a))

#define MMA_TF32(c, a, b)                                                        \
    asm volatile("mma.sync.aligned.m16n8k8.row.col.f32.tf32.tf32.f32 "           \
        "{%0,%1,%2,%3}, {%4,%5,%6,%7}, {%8,%9}, {%0,%1,%2,%3};"                  \
        : "+f"((c)[0]), "+f"((c)[1]), "+f"((c)[2]), "+f"((c)[3])                 \
        : "r"((a)[0]), "r"((a)[1]), "r"((a)[2]), "r"((a)[3]),                    \
          "r"((b)[0]), "r"((b)[1]))

// ---------------- weight prep + scratch zero (fused) ----------------
// grid dim3(16,8) x 256 threads = 32768 threads >= N1
__global__ __launch_bounds__(256)
void k_prep(const float* __restrict__ Ws0, const float* __restrict__ Wn0) {
    // zero the need-mask + counter (independent of the transpose work below)
    {
        int bid  = blockIdx.y * 16 + blockIdx.x;
        int gtid = bid * 256 + threadIdx.x;
        if (gtid < N1) g_need[gtid] = 0;
        if (gtid == 0) g_cnt = 0;
    }
    __shared__ float t[32][33];
    const int bk = blockIdx.x * 32;   // k block (0..511)
    const int bn = blockIdx.y * 32;   // n block (0..255)
    const int tx = threadIdx.x & 31, ty = threadIdx.x >> 5;   // 32 x 8
    const float* W = (bk < 256) ? (Ws0 + (size_t)bk * DHID) : (Wn0 + (size_t)(bk - 256) * DHID);
    #pragma unroll
    for (int i = 0; i < 32; i += 8)
        t[ty + i][tx] = W[(size_t)(ty + i) * DHID + bn + tx];
    __syncthreads();
    #pragma unroll
    for (int i = 0; i < 32; i += 8)
        g_W0t[(size_t)(bn + ty + i) * 512 + bk + tx] = frna(t[tx][ty + i]);
}

// ---------------- mark + compact fused (atomicExch dedup) ----------------
__global__ void k_markcompact(const int* __restrict__ col1) {
    int i = blockIdx.x * 256 + threadIdx.x;
    if (i < N2 * F1) {
        int j = col1[i];
        if (atomicExch(&g_need[j], 1) == 0) {
            int p = atomicAdd(&g_cnt, 1);
            g_rowlist[p] = j;
        }
    }
    if (i < N2) {
        if (atomicExch(&g_need[i], 1) == 0) {
            int p = atomicAdd(&g_cnt, 1);
            g_rowlist[p] = i;
        }
    }
}

// ---------------- layer 0 gather: 4 rows/CTA, 64 threads/row, float4 ----------------
__global__ __launch_bounds__(256)
void k_gather0(const float* __restrict__ emb,
               const int*   __restrict__ gid0,
               const int*   __restrict__ col0) {
    __shared__ int gsh[4][26];
    const int cnt = g_cnt;
    const int rb = blockIdx.x * 4;
    const int tid = threadIdx.x;

    if (tid < 128) {
        int row = tid >> 5, f = tid & 31;
        int r = rb + row;
        if (f < 26 && r < cnt) {
            int j = g_rowlist[r];
            int c = (f == 0) ? j : col0[(size_t)j * F0 + (f - 1)];
            gsh[row][f] = gid0[c];
        }
    }
    __syncthreads();

    const int row = tid >> 6, l = tid & 63;
    const int r = rb + row;
    if (r >= cnt) return;

    const float4* E = (const float4*)emb;   // row stride 64
    float4* V = (float4*)g_V0;              // row stride 128

    float4 s = E[(size_t)gsh[row][0] * 64 + l];
    V[(size_t)r * 128 + l] = frna4(s);

    float4 a0 = {0,0,0,0}, a1 = {0,0,0,0}, a2 = {0,0,0,0}, a3 = {0,0,0,0};
    #pragma unroll
    for (int f = 1; f < 26; f += 4) {
        float4 t0 = E[(size_t)gsh[row][f] * 64 + l];
        a0.x += t0.x; a0.y += t0.y; a0.z += t0.z; a0.w += t0.w;
        if (f + 1 < 26) {
            float4 t1 = E[(size_t)gsh[row][f + 1] * 64 + l];
            a1.x += t1.x; a1.y += t1.y; a1.z += t1.z; a1.w += t1.w;
        }
        if (f + 2 < 26) {
            float4 t2 = E[(size_t)gsh[row][f + 2] * 64 + l];
            a2.x += t2.x; a2.y += t2.y; a2.z += t2.z; a2.w += t2.w;
        }
        if (f + 3 < 26) {
            float4 t3 = E[(size_t)gsh[row][f + 3] * 64 + l];
            a3.x += t3.x; a3.y += t3.y; a3.z += t3.z; a3.w += t3.w;
        }
    }
    const float sc = 1.f / F0;
    float4 acc;
    acc.x = (a0.x + a1.x + a2.x + a3.x) * sc;
    acc.y = (a0.y + a1.y + a2.y + a3.y) * sc;
    acc.z = (a0.z + a1.z + a2.z + a3.z) * sc;
    acc.w = (a0.w + a1.w + a2.w + a3.w) * sc;
    V[(size_t)r * 128 + 64 + l] = frna4(acc);
}

// ---------------- layer 0 GEMM via mma.sync tf32, 3-stage cp.async, 1 sync/iter ----------------
// CTA 128x128, BK=32, 8 warps (2 m x 4 n), warp tile 64x32, m16n8k8.
// SMEM: 3 stages x (A 16KB + B 16KB) = 96KB; meta (jrow+bias) after; +1KB alignment slack.
#define G0_STAGE  32768
#define G0_META   (3 * G0_STAGE)
#define G0_SMEM   (G0_META + 1024 + 1024)

__global__ __launch_bounds__(256, 1)
void k_gemm0_mma(const float* __restrict__ b0) {
    extern __shared__ char smem_raw[];
    const int cnt = g_cnt;
    const int r0 = blockIdx.x * 128;
    if (r0 >= cnt) return;
    const int n0 = blockIdx.y * 128;

    const int tid  = threadIdx.x;
    const int wid  = tid >> 5, lane = tid & 31;
    const int warp_m = wid & 1, warp_n = wid >> 1;

    uint32_t sb0 = smem_u32(smem_raw);
    uint32_t sb  = (sb0 + 1023) & ~1023u;               // 1024-aligned base for swizzle
    char* smem   = smem_raw + (sb - sb0);

    int*   jrow = (int*)(smem + G0_META);
    float* bsh  = (float*)(smem + G0_META + 512);
    if (tid < 128) {
        int r = r0 + tid;
        jrow[tid] = (r < cnt) ? g_rowlist[r] : 0;
        bsh[tid]  = b0[n0 + tid];
    }

    // ldmatrix lane geometry (unchanged from validated round-5 layout)
    const int rowlA  = (lane & 7) + ((lane >> 3) & 1) * 8;
    const int khalfA = lane >> 4;
    const int rowlB  = (lane & 7) + (lane >> 4) * 8;
    const int khalfB = (lane >> 3) & 1;
    const uint32_t axor = (uint32_t)((lane & 7) << 4);

    float acc[4][4][4];
    #pragma unroll
    for (int mt = 0; mt < 4; mt++)
        #pragma unroll
        for (int nt = 0; nt < 4; nt++)
            #pragma unroll
            for (int q = 0; q < 4; q++) acc[mt][nt][q] = 0.f;

    auto load_tile = [&](int kt, int stage) {
        const int k0 = kt * 32;
        uint32_t As = sb + stage * G0_STAGE;
        uint32_t Bs = As + 16384;
        #pragma unroll
        for (int i = 0; i < 4; i++) {
            int v = tid + i * 256;
            int m = v >> 3, kq = v & 7;
            uint32_t off = (uint32_t)(m * 128 + kq * 16);
            off ^= (uint32_t)((m & 7) << 4);
            cpa16(As + off, &g_V0 [(size_t)(r0 + m) * 512 + k0 + kq * 4]);
            cpa16(Bs + off, &g_W0t[(size_t)(n0 + m) * 512 + k0 + kq * 4]);
        }
        CP_COMMIT();
    };

    load_tile(0, 0);
    load_tile(1, 1);

    for (int kt = 0; kt < 16; kt++) {
        if (kt == 15) { CP_WAIT(0); } else { CP_WAIT(1); }
        __syncthreads();                       // stage kt%3 visible; prev-iter readers done

        if (kt + 2 < 16) load_tile(kt + 2, (kt + 2) % 3);   // overwrites stage (kt-1)%3: safe post-sync

        uint32_t As = sb + (kt % 3) * G0_STAGE;
        uint32_t Bs = As + 16384;

        #pragma unroll
        for (int ks = 0; ks < 4; ks++) {
            const int kk = ks * 8;
            uint32_t a[4][4], b[4][2];
            #pragma unroll
            for (int mt = 0; mt < 4; mt++) {
                uint32_t off = (uint32_t)((warp_m * 64 + mt * 16 + rowlA) * 128 + khalfA * 16 + kk * 4);
                LDSM4(a[mt], As + (off ^ axor));
            }
            #pragma unroll
            for (int p = 0; p < 2; p++) {
                uint32_t off = (uint32_t)((warp_n * 32 + p * 16 + rowlB) * 128 + khalfB * 16 + kk * 4);
                uint32_t r[4];
                LDSM4(r, Bs + (off ^ axor));
                b[2 * p][0] = r[0]; b[2 * p][1] = r[1];
                b[2 * p + 1][0] = r[2]; b[2 * p + 1][1] = r[3];
            }
            #pragma unroll
            for (int mt = 0; mt < 4; mt++)
                #pragma unroll
                for (int nt = 0; nt < 4; nt++)
                    MMA_TF32(acc[mt][nt], a[mt], b[nt]);
        }
    }

    // epilogue: bias + relu, scatter rows via jrow
    #pragma unroll
    for (int mt = 0; mt < 4; mt++) {
        #pragma unroll
        for (int h = 0; h < 2; h++) {
            int m = warp_m * 64 + mt * 16 + (lane >> 2) + h * 8;
            int r = r0 + m;
            if (r < cnt) {
                float* Hp = g_H + (size_t)jrow[m] * 256 + n0;
                #pragma unroll
                for (int nt = 0; nt < 4; nt++) {
                    int c = warp_n * 32 + nt * 8 + (lane & 3) * 2;
                    float2 o;
                    o.x = acc[mt][nt][h * 2 + 0] + bsh[c];
                    o.y = acc[mt][nt][h * 2 + 1] + bsh[c + 1];
                    o.x = fmaxf(o.x, 0.f);
                    o.y = fmaxf(o.y, 0.f);
                    *(float2*)&Hp[c] = o;
                }
            }
        }
    }
}

// ---------------- layer 1 gather + neighbor mean ----------------
__global__ void k_gather1(const int* __restrict__ col1) {
    int i = blockIdx.x;
    int t = threadIdx.x;
    g_V1[(size_t)i * 512 + t] = g_H[(size_t)i * 256 + t];
    float acc = 0.f;
    #pragma unroll
    for (int f = 0; f < F1; f++) {
        int c = col1[i * F1 + f];
        acc += g_H[(size_t)c * 256 + t];
    }
    g_V1[(size_t)i * 512 + 256 + t] = acc * (1.f / F1);
}

// ---------------- layer 1 GEMM (split-K=4 into partials, deterministic, f32) ----------------
__global__ __launch_bounds__(256)
void k_gemm1(const float* __restrict__ Wself, const float* __restrict__ Wneigh) {
    const int r0 = blockIdx.x * 32;
    const int ks = blockIdx.y;
    const int kbase = ks * 128;

    __shared__ float As[32][17];
    __shared__ float Bs[16][128];

    const int tid = threadIdx.x;
    const int tx = tid & 31, ty = tid >> 5;

    float acc[4][4];
    #pragma unroll
    for (int i = 0; i < 4; i++)
        #pragma unroll
        for (int j = 0; j < 4; j++) acc[i][j] = 0.f;

    for (int kt = 0; kt < 8; kt++) {
        const int k0 = kbase + kt * 16;
        #pragma unroll
        for (int i = 0; i < 2; i++) {
            int v = tid + i * 256;
            int kk = v & 15, m = v >> 4;
            As[m][kk] = g_V1[(size_t)(r0 + m) * 512 + k0 + kk];
        }
        const float* B = (k0 < 256) ? (Wself + (size_t)k0 * NCLS)
                                    : (Wneigh + (size_t)(k0 - 256) * NCLS);
        #pragma unroll
        for (int i = 0; i < 2; i++) {
            int v = tid + i * 256;
            int kk = v >> 5, c4 = v & 31;
            *(float4*)&Bs[kk][c4 * 4] = *(const float4*)&B[(size_t)kk * NCLS + c4 * 4];
        }
        __syncthreads();

        #pragma unroll
        for (int kk = 0; kk < 16; kk++) {
            float a[4], b[4];
            #pragma unroll
            for (int s = 0; s < 4; s++) {
                a[s] = As[ty * 4 + s][kk];
                b[s] = Bs[kk][tx * 4 + s];
            }
            #pragma unroll
            for (int i = 0; i < 4; i++)
                #pragma unroll
                for (int j = 0; j < 4; j++) acc[i][j] += a[i] * b[j];
        }
        __syncthreads();
    }

    float* P = g_P + (size_t)ks * N2 * NCLS;
    #pragma unroll
    for (int i = 0; i < 4; i++) {
        int r = r0 + ty * 4 + i;
        #pragma unroll
        for (int j = 0; j < 4; j++)
            P[(size_t)r * NCLS + tx * 4 + j] = acc[i][j];
    }
}

__global__ void k_reduce(const float* __restrict__ b1, float* __restrict__ out) {
    int i = blockIdx.x * 256 + threadIdx.x;
    float v = g_P[i]
            + g_P[(size_t)N2 * NCLS + i]
            + g_P[(size_t)2 * N2 * NCLS + i]
            + g_P[(size_t)3 * N2 * NCLS + i]
            + b1[i & (NCLS - 1)];
    out[i] = v;
}

// ---------------- launch ----------------
extern "C" void kernel_launch(void* const* d_in, const int* in_sizes, int n_in,
                              void* d_out, int out_size) {
    const float* emb  = (const float*)d_in[0];
    const int*   gid0 = (const int*)  d_in[1];
    const int*   col0 = (const int*)  d_in[2];
    const int*   col1 = (const int*)  d_in[3];
    const float* Ws0  = (const float*)d_in[4];
    const float* Wn0  = (const float*)d_in[5];
    const float* b0   = (const float*)d_in[6];
    const float* Ws1  = (const float*)d_in[7];
    const float* Wn1  = (const float*)d_in[8];
    const float* b1   = (const float*)d_in[9];
    float* out = (float*)d_out;

    cudaFuncSetAttribute(k_gemm0_mma, cudaFuncAttributeMaxDynamicSharedMemorySize, G0_SMEM);

    k_prep       <<<dim3(16, 8), 256>>>(Ws0, Wn0);
    k_markcompact<<<(N2 * F1 + 255) / 256, 256>>>(col1);
    k_gather0    <<<(N1 + 3) / 4, 256>>>(emb, gid0, col0);
    k_gemm0_mma  <<<dim3((N1 + 127) / 128, DHID / 128), 256, G0_SMEM>>>(b0);
    k_gather1    <<<N2, 256>>>(col1);
    k_gemm1      <<<dim3(N2 / 32, 4), 256>>>(Ws1, Wn1);
    k_reduce     <<<(N2 * NCLS) / 256, 256>>>(b1, out);
}